// round 15
// baseline (speedup 1.0000x reference)
#include <cuda_runtime.h>
#include <math.h>

#define B_  32
#define S_  50
#define Q_  75
#define T_  128
#define F_  64
#define D_  256
#define KW  5
#define NS  (B_*S_)          // 1600 support samples
#define NQ  (B_*Q_)          // 2400 query samples
#define NTOT (NS+NQ)         // 4000
#define POOLB (NTOT/4)       // 1000 pool blocks
#define GRAMB F_             // 64 gram blocks
#define PROTB B_             // 32 proto blocks
#define QPB   16
#define DISTB (NQ/QPB)       // 150 dist blocks
#define C1_TARGET (POOLB + GRAMB)

// Scratch (device globals: allocation-free per harness rules)
__device__ float g_spooled[NS * F_];     // pooled support
__device__ float g_qfeat[NQ * F_];       // pooled queries
__device__ float g_G[F_ * F_];           // Gram G = W W^T
__device__ float g_h[B_ * KW * F_];      // h_k = G p_k
__device__ float g_c[B_ * KW];           // c_k = p_k . h_k
__device__ unsigned int g_cnt1, g_cnt2;  // phase counters

__global__ void init_counters() { g_cnt1 = 0u; g_cnt2 = 0u; }

// Unioned shared memory (sized by the dist branch, the largest user)
struct DistSmem {
    float Gs[F_ * F_];        // 16 KB
    float Qs[QPB][68];        // padded rows
    float hsh[2][KW][F_];
    float csh[2][KW];
};
struct PoolSmem  { float4 part[4][2][16]; };
struct ProtoSmem { int ys[S_]; float psh[KW][F_]; float csh[KW][F_]; };

__device__ __forceinline__ void release_count(unsigned int* ctr) {
    __threadfence();
    __syncthreads();
    if (threadIdx.x == 0) atomicAdd(ctr, 1u);
}
__device__ __forceinline__ void acquire_spin(unsigned int* ctr, unsigned int target) {
    if (threadIdx.x == 0) {
        while (*(volatile unsigned int*)ctr < target) __nanosleep(64);
    }
    __syncthreads();
}

__global__ void __launch_bounds__(256) fused_kernel(const float* __restrict__ sx,
                                                    const float* __restrict__ qx,
                                                    const float* __restrict__ Wm,
                                                    const int*   __restrict__ y,
                                                    float*       __restrict__ out) {
    __shared__ __align__(16) char smraw[sizeof(DistSmem)];
    int tid = threadIdx.x;
    unsigned int bid = blockIdx.x;

    if (bid < POOLB) {
        // ================= pool (R12-proven body: regs 32, occ-insensitive) =====
        PoolSmem* sm = reinterpret_cast<PoolSmem*>(smraw);
        int lane    = tid & 31;
        int s_local = tid >> 6;
        int wis     = (tid >> 5) & 1;
        int th      = lane >> 4;
        int f4      = lane & 15;

        int sn = bid * 4 + s_local;
        const float4* src;
        float4* dstbase;
        if (sn < NS) {
            src     = reinterpret_cast<const float4*>(sx) + (size_t)sn * (T_ * F_ / 4);
            dstbase = reinterpret_cast<float4*>(g_spooled);
        } else {
            src     = reinterpret_cast<const float4*>(qx) + (size_t)(sn - NS) * (T_ * F_ / 4);
            dstbase = reinterpret_cast<float4*>(g_qfeat) - (size_t)NS * 16;
        }

        const float4* p = src + (wis * 64 + th) * 16 + f4;
        float4 a0 = make_float4(0.f,0.f,0.f,0.f);
        float4 a1 = make_float4(0.f,0.f,0.f,0.f);
        #pragma unroll 4
        for (int i = 0; i < 32; i += 2) {
            float4 v0 = p[(2 * i)     * 16];
            float4 v1 = p[(2 * i + 2) * 16];
            a0.x += v0.x; a0.y += v0.y; a0.z += v0.z; a0.w += v0.w;
            a1.x += v1.x; a1.y += v1.y; a1.z += v1.z; a1.w += v1.w;
        }
        float4 a;
        a.x = a0.x + a1.x; a.y = a0.y + a1.y; a.z = a0.z + a1.z; a.w = a0.w + a1.w;
        a.x += __shfl_xor_sync(0xffffffffu, a.x, 16);
        a.y += __shfl_xor_sync(0xffffffffu, a.y, 16);
        a.z += __shfl_xor_sync(0xffffffffu, a.z, 16);
        a.w += __shfl_xor_sync(0xffffffffu, a.w, 16);

        if (th == 0) sm->part[s_local][wis][f4] = a;
        __syncthreads();

        if (tid < 64) {
            int s = tid >> 4;
            int f = tid & 15;
            float4 u = sm->part[s][0][f];
            float4 v = sm->part[s][1][f];
            const float inv = 1.0f / (float)T_;
            float4 r;
            r.x = (u.x + v.x) * inv;
            r.y = (u.y + v.y) * inv;
            r.z = (u.z + v.z) * inv;
            r.w = (u.w + v.w) * inv;
            dstbase[(bid * 4 + s) * 16 + f] = r;
        }
        release_count(&g_cnt1);
        return;
    }

    if (bid < POOLB + GRAMB) {
        // ================= gram: G row i =======================================
        int i    = bid - POOLB;
        int warp = tid >> 5;
        int lane = tid & 31;

        float wi[8];
        #pragma unroll
        for (int u = 0; u < 8; u++)
            wi[u] = Wm[i * D_ + lane + 32 * u];

        float s[8];
        #pragma unroll
        for (int jj = 0; jj < 8; jj++) s[jj] = 0.f;
        #pragma unroll
        for (int u = 0; u < 8; u++) {
            #pragma unroll
            for (int jj = 0; jj < 8; jj++)
                s[jj] = fmaf(wi[u], Wm[(warp * 8 + jj) * D_ + lane + 32 * u], s[jj]);
        }
        #pragma unroll
        for (int jj = 0; jj < 8; jj++) {
            #pragma unroll
            for (int off = 16; off > 0; off >>= 1)
                s[jj] += __shfl_xor_sync(0xffffffffu, s[jj], off);
        }
        if (lane == 0) {
            #pragma unroll
            for (int jj = 0; jj < 8; jj++)
                g_G[i * F_ + warp * 8 + jj] = s[jj];
        }
        release_count(&g_cnt1);
        return;
    }

    if (bid < POOLB + GRAMB + PROTB) {
        // ================= proto: waits for pool+gram ==========================
        ProtoSmem* sm = reinterpret_cast<ProtoSmem*>(smraw);
        int b = bid - (POOLB + GRAMB);

        acquire_spin(&g_cnt1, C1_TARGET);

        if (tid < S_) sm->ys[tid] = y[b * S_ + tid];
        __syncthreads();

        if (tid < F_) {
            int f = tid;
            float a0=0.f,a1=0.f,a2=0.f,a3=0.f,a4=0.f;
            int   c0=0,c1=0,c2=0,c3=0,c4=0;
            #pragma unroll 10
            for (int s = 0; s < S_; s++) {
                float v = g_spooled[(b * S_ + s) * F_ + f];
                int l = sm->ys[s];
                if (l == 0) { a0 += v; c0++; }
                if (l == 1) { a1 += v; c1++; }
                if (l == 2) { a2 += v; c2++; }
                if (l == 3) { a3 += v; c3++; }
                if (l == 4) { a4 += v; c4++; }
            }
            sm->psh[0][f] = c0 ? a0 / (float)c0 : 0.f;
            sm->psh[1][f] = c1 ? a1 / (float)c1 : 0.f;
            sm->psh[2][f] = c2 ? a2 / (float)c2 : 0.f;
            sm->psh[3][f] = c3 ? a3 / (float)c3 : 0.f;
            sm->psh[4][f] = c4 ? a4 / (float)c4 : 0.f;
        }
        __syncthreads();

        if (tid < F_) {
            int f = tid;
            float hk[KW];
            #pragma unroll
            for (int k = 0; k < KW; k++) hk[k] = 0.f;
            #pragma unroll 8
            for (int i = 0; i < F_; i++) {
                float gi = g_G[i * F_ + f];   // symmetric -> coalesced rows
                #pragma unroll
                for (int k = 0; k < KW; k++)
                    hk[k] = fmaf(gi, sm->psh[k][i], hk[k]);
            }
            #pragma unroll
            for (int k = 0; k < KW; k++) {
                g_h[(b * KW + k) * F_ + f] = hk[k];
                sm->csh[k][f] = sm->psh[k][f] * hk[k];
            }
        }
        __syncthreads();

        if (tid < 32) {
            #pragma unroll
            for (int k = 0; k < KW; k++) {
                float v = sm->csh[k][tid] + sm->csh[k][tid + 32];
                #pragma unroll
                for (int off = 16; off > 0; off >>= 1)
                    v += __shfl_xor_sync(0xffffffffu, v, off);
                if (tid == 0) g_c[b * KW + k] = v;
            }
        }
        release_count(&g_cnt2);
        return;
    }

    // ================= dist: waits for proto (implies pool+gram done) ==========
    {
        DistSmem* ds = reinterpret_cast<DistSmem*>(smraw);
        int q_local = tid >> 4;
        int jg      = tid & 15;
        int dbid    = bid - (POOLB + GRAMB + PROTB);
        int qbase   = dbid * QPB;
        int bq      = qbase + q_local;
        int b0      = qbase / Q_;
        int b1      = (qbase + QPB - 1) / Q_;

        acquire_spin(&g_cnt2, PROTB);

        {   // stage G, query rows, h, c
            const float4* gsrc = reinterpret_cast<const float4*>(g_G);
            float4* gdst = reinterpret_cast<float4*>(ds->Gs);
            #pragma unroll
            for (int u = 0; u < 4; u++) gdst[tid + 256 * u] = gsrc[tid + 256 * u];

            int row = tid >> 4, c = tid & 15;
            float4 qv = reinterpret_cast<const float4*>(g_qfeat)[(qbase + row) * 16 + c];
            *reinterpret_cast<float4*>(&ds->Qs[row][c * 4]) = qv;

            float* hflat = &ds->hsh[0][0][0];
            for (int i = tid; i < 2 * KW * F_; i += 256) {
                int eb = i / (KW * F_);
                int be = eb ? b1 : b0;
                hflat[i] = g_h[be * KW * F_ + (i - eb * KW * F_)];
            }
            if (tid < 2 * KW) {
                int eb = tid / KW;
                ds->csh[eb][tid % KW] = g_c[(eb ? b1 : b0) * KW + tid % KW];
            }
        }
        __syncthreads();

        float e0 = 0.f, e1 = 0.f, e2 = 0.f, e3 = 0.f;
        #pragma unroll 16
        for (int k = 0; k < F_; k++) {
            float qk = ds->Qs[q_local][k];
            float4 g = *reinterpret_cast<const float4*>(&ds->Gs[k * F_ + jg * 4]);
            e0 = fmaf(g.x, qk, e0);
            e1 = fmaf(g.y, qk, e1);
            e2 = fmaf(g.z, qk, e2);
            e3 = fmaf(g.w, qk, e3);
        }
        float4 qj = *reinterpret_cast<const float4*>(&ds->Qs[q_local][jg * 4]);
        float a = e0 * qj.x + e1 * qj.y + e2 * qj.z + e3 * qj.w;

        int b  = bq / Q_;
        int eb = b - b0;
        float s[KW];
        #pragma unroll
        for (int k = 0; k < KW; k++) {
            float4 h4 = *reinterpret_cast<const float4*>(&ds->hsh[eb][k][jg * 4]);
            s[k] = qj.x * h4.x + qj.y * h4.y + qj.z * h4.z + qj.w * h4.w;
        }

        #pragma unroll
        for (int off = 8; off > 0; off >>= 1) {
            a += __shfl_xor_sync(0xffffffffu, a, off);
            #pragma unroll
            for (int k = 0; k < KW; k++)
                s[k] += __shfl_xor_sync(0xffffffffu, s[k], off);
        }

        if (jg == 0) {
            #pragma unroll
            for (int k = 0; k < KW; k++)
                out[bq * KW + k] = -sqrtf(fmaxf(a - 2.f * s[k] + ds->csh[eb][k], 0.f));
        }
    }
}

// ---------------------------------------------------------------------------
// Inputs (metadata order): support_x f32, support_y i32, query_x f32, W f32, b f32
// Output: f32 [B*Q, KW] = [2400, 5]
// ---------------------------------------------------------------------------
extern "C" void kernel_launch(void* const* d_in, const int* in_sizes, int n_in,
                              void* d_out, int out_size) {
    const float* sx = (const float*)d_in[0];
    const int*   sy = (const int*)  d_in[1];
    const float* qx = (const float*)d_in[2];
    const float* Wm = (const float*)d_in[3];
    float* out = (float*)d_out;

    init_counters<<<1, 1>>>();
    fused_kernel<<<POOLB + GRAMB + PROTB + DISTB, 256>>>(sx, qx, Wm, sy, out);
}